// round 3
// baseline (speedup 1.0000x reference)
#include <cuda_runtime.h>

#define DD   64
#define LL   3
#define NMAX 100000
#define EMAX 1200000

// ---------------- scratch (device globals: allocation-free) ----------------
__device__ float g_M[NMAX * DD];      // mlp(h) per node (message values)
__device__ float g_G[NMAX * DD];      // aggregated messages per node
__device__ float g_H[NMAX * DD];      // current hidden state
__device__ int   g_cnt[NMAX];         // per-node in-degree / scatter cursor
__device__ int   g_rowptr[NMAX + 1];  // CSR row pointers (by edge row / dst)
__device__ int   g_ecol[EMAX];        // CSR column indices (src node per edge)
__device__ int   g_bsums[1024];       // scan block sums

// ---------------- packed f32x2 helpers ----------------
__device__ __forceinline__ unsigned long long pack2(float a, float b) {
    unsigned long long r;
    asm("mov.b64 %0, {%1, %2};" : "=l"(r) : "f"(a), "f"(b));
    return r;
}
__device__ __forceinline__ void unpack2(unsigned long long v, float& a, float& b) {
    asm("mov.b64 {%0, %1}, %2;" : "=f"(a), "=f"(b) : "l"(v));
}
__device__ __forceinline__ void fma2(unsigned long long& d,
                                     unsigned long long a, unsigned long long b) {
    asm("fma.rn.f32x2 %0, %1, %2, %0;" : "+l"(d) : "l"(a), "l"(b));
}
__device__ __forceinline__ void lds_v2u64(unsigned addr,
                                          unsigned long long& a, unsigned long long& b) {
    asm("ld.shared.v2.u64 {%0, %1}, [%2];" : "=l"(a), "=l"(b) : "r"(addr));
}

// ---------------- CSR construction ----------------
__global__ void zero_int_kernel(int* p, int n) {
    int i = blockIdx.x * blockDim.x + threadIdx.x;
    if (i < n) p[i] = 0;
}

__global__ void hist_kernel(const int* __restrict__ rows, int E) {
    int e = blockIdx.x * blockDim.x + threadIdx.x;
    if (e < E) atomicAdd(&g_cnt[rows[e]], 1);
}

__global__ void scan1_kernel(int n) {
    __shared__ int sh[1024];
    int i = blockIdx.x * 1024 + threadIdx.x;
    int v = (i < n) ? g_cnt[i] : 0;
    sh[threadIdx.x] = v;
    __syncthreads();
    for (int off = 1; off < 1024; off <<= 1) {
        int t = (threadIdx.x >= off) ? sh[threadIdx.x - off] : 0;
        __syncthreads();
        sh[threadIdx.x] += t;
        __syncthreads();
    }
    if (i < n) g_rowptr[i] = sh[threadIdx.x] - v;       // exclusive within block
    if (threadIdx.x == 1023) g_bsums[blockIdx.x] = sh[1023];
}

__global__ void scan2_kernel(int nb) {
    __shared__ int sh[1024];
    int v = (threadIdx.x < nb) ? g_bsums[threadIdx.x] : 0;
    sh[threadIdx.x] = v;
    __syncthreads();
    for (int off = 1; off < 1024; off <<= 1) {
        int t = (threadIdx.x >= off) ? sh[threadIdx.x - off] : 0;
        __syncthreads();
        sh[threadIdx.x] += t;
        __syncthreads();
    }
    if (threadIdx.x < nb) g_bsums[threadIdx.x] = sh[threadIdx.x] - v;  // exclusive
}

__global__ void scan3_kernel(int n, int E) {
    int i = blockIdx.x * blockDim.x + threadIdx.x;
    if (i < n) g_rowptr[i] += g_bsums[i >> 10];
    if (i == n) g_rowptr[n] = E;
}

__global__ void scatter_kernel(const int* __restrict__ rows,
                               const int* __restrict__ cols, int E) {
    int e = blockIdx.x * blockDim.x + threadIdx.x;
    if (e < E) {
        int r = rows[e];
        int pos = g_rowptr[r] + atomicAdd(&g_cnt[r], 1);
        g_ecol[pos] = cols[e];
    }
}

// ---------------- fused 2-layer MLP: out = relu((in(+add)) @ W1 + b1) @ W2 + b2 ---
__global__ __launch_bounds__(256, 1)
void mlp_kernel(const float* __restrict__ in, const float* __restrict__ add,
                const float* __restrict__ W1, const float* __restrict__ b1,
                const float* __restrict__ W2, const float* __restrict__ b2,
                float* __restrict__ out, int n) {
    __shared__ float w1s[DD * DD];
    __shared__ float w2s[DD * DD];
    __shared__ float bsh[2 * DD];
    for (int i = threadIdx.x; i < DD * DD; i += 256) {
        w1s[i] = W1[i];
        w2s[i] = W2[i];
    }
    if (threadIdx.x < DD)            bsh[threadIdx.x] = b1[threadIdx.x];
    else if (threadIdx.x < 2 * DD)   bsh[threadIdx.x] = b2[threadIdx.x - DD];
    __syncthreads();

    int r = blockIdx.x * blockDim.x + threadIdx.x;
    if (r >= n) return;

    float x[DD];
    {
        const float4* iv = (const float4*)(in + (long)r * DD);
#pragma unroll
        for (int j = 0; j < 16; j++) {
            float4 v = iv[j];
            x[4 * j] = v.x; x[4 * j + 1] = v.y; x[4 * j + 2] = v.z; x[4 * j + 3] = v.w;
        }
        if (add) {
            const float4* av = (const float4*)(add + (long)r * DD);
#pragma unroll
            for (int j = 0; j < 16; j++) {
                float4 v = av[j];
                x[4 * j] += v.x; x[4 * j + 1] += v.y; x[4 * j + 2] += v.z; x[4 * j + 3] += v.w;
            }
        }
    }

    unsigned w1a = (unsigned)__cvta_generic_to_shared(w1s);
    unsigned w2a = (unsigned)__cvta_generic_to_shared(w2s);

    unsigned long long acc[32];
#pragma unroll
    for (int j = 0; j < 32; j++) acc[j] = pack2(bsh[2 * j], bsh[2 * j + 1]);

    // stage 1: acc = x @ W1 + b1
#pragma unroll
    for (int k = 0; k < DD; k++) {
        unsigned long long xk = pack2(x[k], x[k]);
        unsigned rowa = w1a + k * DD * 4;
#pragma unroll
        for (int j = 0; j < 16; j++) {
            unsigned long long a, b;
            lds_v2u64(rowa + j * 16, a, b);
            fma2(acc[2 * j], xk, a);
            fma2(acc[2 * j + 1], xk, b);
        }
    }

    // relu -> x
#pragma unroll
    for (int j = 0; j < 32; j++) {
        float a, b;
        unpack2(acc[j], a, b);
        x[2 * j]     = fmaxf(a, 0.0f);
        x[2 * j + 1] = fmaxf(b, 0.0f);
    }

#pragma unroll
    for (int j = 0; j < 32; j++) acc[j] = pack2(bsh[DD + 2 * j], bsh[DD + 2 * j + 1]);

    // stage 2: acc = relu(...) @ W2 + b2
#pragma unroll
    for (int k = 0; k < DD; k++) {
        unsigned long long xk = pack2(x[k], x[k]);
        unsigned rowa = w2a + k * DD * 4;
#pragma unroll
        for (int j = 0; j < 16; j++) {
            unsigned long long a, b;
            lds_v2u64(rowa + j * 16, a, b);
            fma2(acc[2 * j], xk, a);
            fma2(acc[2 * j + 1], xk, b);
        }
    }

    float4* ov = (float4*)(out + (long)r * DD);
#pragma unroll
    for (int j = 0; j < 16; j++) {
        float a, b, c, d;
        unpack2(acc[2 * j], a, b);
        unpack2(acc[2 * j + 1], c, d);
        ov[j] = make_float4(a, b, c, d);
    }
}

// ---------------- final projection: out = in @ Wf + bf ----------------
__global__ __launch_bounds__(256, 1)
void final_kernel(const float* __restrict__ in, const float* __restrict__ W,
                  const float* __restrict__ b, float* __restrict__ out, int n) {
    __shared__ float ws[DD * DD];
    __shared__ float bsh[DD];
    for (int i = threadIdx.x; i < DD * DD; i += 256) ws[i] = W[i];
    if (threadIdx.x < DD) bsh[threadIdx.x] = b[threadIdx.x];
    __syncthreads();

    int r = blockIdx.x * blockDim.x + threadIdx.x;
    if (r >= n) return;

    float x[DD];
    {
        const float4* iv = (const float4*)(in + (long)r * DD);
#pragma unroll
        for (int j = 0; j < 16; j++) {
            float4 v = iv[j];
            x[4 * j] = v.x; x[4 * j + 1] = v.y; x[4 * j + 2] = v.z; x[4 * j + 3] = v.w;
        }
    }
    unsigned wa = (unsigned)__cvta_generic_to_shared(ws);
    unsigned long long acc[32];
#pragma unroll
    for (int j = 0; j < 32; j++) acc[j] = pack2(bsh[2 * j], bsh[2 * j + 1]);
#pragma unroll
    for (int k = 0; k < DD; k++) {
        unsigned long long xk = pack2(x[k], x[k]);
        unsigned rowa = wa + k * DD * 4;
#pragma unroll
        for (int j = 0; j < 16; j++) {
            unsigned long long a, b;
            lds_v2u64(rowa + j * 16, a, b);
            fma2(acc[2 * j], xk, a);
            fma2(acc[2 * j + 1], xk, b);
        }
    }
    float4* ov = (float4*)(out + (long)r * DD);
#pragma unroll
    for (int j = 0; j < 16; j++) {
        float a, b, c, d;
        unpack2(acc[2 * j], a, b);
        unpack2(acc[2 * j + 1], c, d);
        ov[j] = make_float4(a, b, c, d);
    }
}

// ---------------- gather-side segment sum: G[v] = sum_{e: row=v} M[col_e] ----
__global__ __launch_bounds__(256)
void agg_kernel(const float* __restrict__ Msrc, float* __restrict__ G, int n) {
    int t = blockIdx.x * blockDim.x + threadIdx.x;
    int w = t >> 5;
    int lane = t & 31;
    if (w >= n) return;
    int s = g_rowptr[w];
    int e = g_rowptr[w + 1];
    float a0 = 0.0f, a1 = 0.0f;
    for (int j = s; j < e; j++) {
        int c = g_ecol[j];
        const float2* mr = (const float2*)(Msrc + (long)c * DD);
        float2 v = __ldg(&mr[lane]);
        a0 += v.x;
        a1 += v.y;
    }
    float2* gr = (float2*)(G + (long)w * DD);
    gr[lane] = make_float2(a0, a1);
}

// ---------------- launch ----------------
extern "C" void kernel_launch(void* const* d_in, const int* in_sizes, int n_in,
                              void* d_out, int out_size) {
    const float* x  = (const float*)d_in[0];
    const int* eidx = (const int*)d_in[1];
    const float* W1 = (const float*)d_in[2];
    const float* b1 = (const float*)d_in[3];
    const float* W2 = (const float*)d_in[4];
    const float* b2 = (const float*)d_in[5];
    const float* Wf = (const float*)d_in[6];
    const float* bf = (const float*)d_in[7];

    int n = in_sizes[0] / DD;
    int E = in_sizes[1] / 2;
    const int* rows = eidx;      // destination (segment id)
    const int* cols = eidx + E;  // source (gather id)

    float *M, *G, *H;
    int* cnt;
    cudaGetSymbolAddress((void**)&M, g_M);
    cudaGetSymbolAddress((void**)&G, g_G);
    cudaGetSymbolAddress((void**)&H, g_H);
    cudaGetSymbolAddress((void**)&cnt, g_cnt);

    const int TB = 256;
    int nb_n = (n + TB - 1) / TB;
    int nb_e = (E + TB - 1) / TB;
    int nb_scan = (n + 1023) / 1024;

    // CSR build (deterministic per call; captured into the graph)
    zero_int_kernel<<<nb_n, TB>>>(cnt, n);
    hist_kernel<<<nb_e, TB>>>(rows, E);
    scan1_kernel<<<nb_scan, 1024>>>(n);
    scan2_kernel<<<1, 1024>>>(nb_scan);
    scan3_kernel<<<(n + 1 + TB - 1) / TB, TB>>>(n, E);
    zero_int_kernel<<<nb_n, TB>>>(cnt, n);
    scatter_kernel<<<nb_e, TB>>>(rows, cols, E);

    const float* h = x;
    for (int l = 0; l < LL; l++) {
        const float* w1 = W1 + l * DD * DD;
        const float* bb1 = b1 + l * DD;
        const float* w2 = W2 + l * DD * DD;
        const float* bb2 = b2 + l * DD;
        // messages: M = mlp(h)  (mlp(h[col]) == mlp(h)[col])
        mlp_kernel<<<nb_n, TB>>>(h, nullptr, w1, bb1, w2, bb2, M, n);
        // aggregate: G[v] = sum over incoming edges of M[col]
        agg_kernel<<<(n * 32 + TB - 1) / TB, TB>>>(M, G, n);
        // combine: H = mlp(h + G)   (in-place safe: row-private read-then-write)
        mlp_kernel<<<nb_n, TB>>>(h, G, w1, bb1, w2, bb2, H, n);
        h = H;
    }
    final_kernel<<<nb_n, TB>>>(h, Wf, bf, (float*)d_out, n);
}